// round 10
// baseline (speedup 1.0000x reference)
#include <cuda_runtime.h>

// GCN via bucket-then-gather (no float atomics):
//   1. k_zero_deg     : deg[] = 0
//   2. k_bucket       : per-dst buckets of src ids (int atomics for cursors)
//   3. k_gather1      : agg1[d] = sum_{e: dst=d} feat[src[e]]   (pure gather)
//   4. k_mlp          : t = relu(agg1@W1+b1) @ W2   (register-tiled, fused)
//   5. k_gather2_sm   : out[d] = softmax(sum t[src] + b2)       (fused)

#define NMAX 100000
#define CAP  128   // max bucket size; dst-degree ~ Poisson(16), P(>=128) ~ 1e-70

__device__ int   g_deg  [NMAX];
__device__ int   g_slots[(size_t)NMAX * CAP];
__device__ __align__(16) float g_agg1[(size_t)NMAX * 64];
__device__ __align__(16) float g_t   [(size_t)NMAX * 16];

// ---------------------------------------------------------------------------
__global__ void k_zero_deg(int n) {
    int i = blockIdx.x * blockDim.x + threadIdx.x;
    if (i < n) g_deg[i] = 0;
}

// ---------------------------------------------------------------------------
// Build buckets: slots[d*CAP + pos] = src.  Int atomics, spread addresses.
__global__ void k_bucket(const int* __restrict__ src,
                         const int* __restrict__ dst, int E) {
    int e = blockIdx.x * blockDim.x + threadIdx.x;
    if (e >= E) return;
    int s = __ldg(src + e);
    int d = __ldg(dst + e);
    int pos = atomicAdd(&g_deg[d], 1);
    if (pos < CAP) g_slots[d * CAP + pos] = s;
}

// ---------------------------------------------------------------------------
// Layer-1 aggregation: 16 threads per node, one float4 column each.
__global__ void __launch_bounds__(256) k_gather1(const float* __restrict__ feat,
                                                 int N) {
    int grp  = blockIdx.x * 16 + (threadIdx.x >> 4);
    int q    = threadIdx.x & 15;
    if (grp >= N) return;

    int degd = min(__ldg(&g_deg[grp]), CAP);
    const int* sl = g_slots + grp * CAP;
    const float4* f4 = reinterpret_cast<const float4*>(feat);

    float4 acc = make_float4(0.f, 0.f, 0.f, 0.f);
    if (degd > 0) {
        int s = __ldg(sl);
        for (int j = 0; j < degd - 1; j++) {
            int snext = __ldg(sl + j + 1);          // prefetch next slot id
            float4 v = __ldg(f4 + (size_t)s * 16 + q);
            acc.x += v.x; acc.y += v.y; acc.z += v.z; acc.w += v.w;
            s = snext;
        }
        float4 v = __ldg(f4 + (size_t)s * 16 + q);
        acc.x += v.x; acc.y += v.y; acc.z += v.z; acc.w += v.w;
    }
    reinterpret_cast<float4*>(g_agg1)[(size_t)grp * 16 + q] = acc;
}

// ---------------------------------------------------------------------------
// Register-tiled MLP. Block = 192 threads handles 96 rows.
// Layer 1: 2 threads per row, each computes 32 of 64 h-columns (acc[32]).
//   Per k-step: 8x LDS.128 weights (broadcast across rows) + 32 FMA -> ~79% FMA.
// Layer 2: h reused via the x smem tile (barrier-protected), 8 outputs/thread.
// Smem: xs 96x68f (pad->2-way max conflict) 26.1KB + W1 16.4KB + W2 4.1KB +
//       b1 0.25KB = 46.8KB static. Regs ~60 -> much higher occupancy than v1.
#define MLP_BR  96
#define MLP_THR 192
#define XSTR    17   // float4 row stride (= 68 floats, 272B, 16B-aligned, pad)

__global__ void __launch_bounds__(MLP_THR) k_mlp(const float* __restrict__ W1,
                                                 const float* __restrict__ b1,
                                                 const float* __restrict__ W2,
                                                 int N) {
    __shared__ float4 xs [MLP_BR * XSTR];   // x tile, reused for h tile
    __shared__ float4 sW1[64 * 16];         // W1 [64][64] as float4
    __shared__ float4 sW2[64 * 4];          // W2 [64][16] as float4
    __shared__ float  sb1[64];

    int tid = threadIdx.x;
    for (int i = tid; i < 64 * 16; i += MLP_THR)
        sW1[i] = __ldg(reinterpret_cast<const float4*>(W1) + i);
    for (int i = tid; i < 64 * 4; i += MLP_THR)
        sW2[i] = __ldg(reinterpret_cast<const float4*>(W2) + i);
    if (tid < 64) sb1[tid] = b1[tid];

    int row0 = blockIdx.x * MLP_BR;

    // Stage x tile (coalesced float4 reads from g_agg1).
    for (int i = tid; i < MLP_BR * 16; i += MLP_THR) {
        int r = i >> 4, c = i & 15;
        float4 v = make_float4(0.f, 0.f, 0.f, 0.f);
        if (row0 + r < N)
            v = __ldg(reinterpret_cast<const float4*>(g_agg1) +
                      (size_t)(row0 + r) * 16 + c);
        xs[r * XSTR + c] = v;
    }
    __syncthreads();

    int row  = tid >> 1;        // 0..95
    int half = tid & 1;         // col half: 0 -> cols 0..31, 1 -> cols 32..63

    // ---- Layer 1: acc[c] = b1 + sum_k x[k] * W1[k][half*32 + c] ----
    float acc[32];
    #pragma unroll
    for (int c = 0; c < 32; c++) acc[c] = sb1[half * 32 + c];

    #pragma unroll 1
    for (int k4 = 0; k4 < 16; k4++) {
        float4 xv = xs[row * XSTR + k4];
        float xe[4] = {xv.x, xv.y, xv.z, xv.w};
        #pragma unroll
        for (int e = 0; e < 4; e++) {
            int k = k4 * 4 + e;
            float x = xe[e];
            #pragma unroll
            for (int c8 = 0; c8 < 8; c8++) {
                float4 w = sW1[k * 16 + half * 8 + c8];
                acc[c8 * 4 + 0] = fmaf(x, w.x, acc[c8 * 4 + 0]);
                acc[c8 * 4 + 1] = fmaf(x, w.y, acc[c8 * 4 + 1]);
                acc[c8 * 4 + 2] = fmaf(x, w.z, acc[c8 * 4 + 2]);
                acc[c8 * 4 + 3] = fmaf(x, w.w, acc[c8 * 4 + 3]);
            }
        }
    }
    #pragma unroll
    for (int c = 0; c < 32; c++) acc[c] = fmaxf(acc[c], 0.f);

    // ---- Write h back into the x tile (all layer-1 reads are done) ----
    __syncthreads();
    #pragma unroll
    for (int c8 = 0; c8 < 8; c8++)
        xs[row * XSTR + half * 8 + c8] =
            make_float4(acc[c8 * 4 + 0], acc[c8 * 4 + 1],
                        acc[c8 * 4 + 2], acc[c8 * 4 + 3]);
    __syncthreads();

    // ---- Layer 2: o[j] = sum_k h[k] * W2[k][half*8 + j] ----
    float o[8];
    #pragma unroll
    for (int j = 0; j < 8; j++) o[j] = 0.f;

    #pragma unroll 1
    for (int k4 = 0; k4 < 16; k4++) {
        float4 hv = xs[row * XSTR + k4];
        float he[4] = {hv.x, hv.y, hv.z, hv.w};
        #pragma unroll
        for (int e = 0; e < 4; e++) {
            int k = k4 * 4 + e;
            float h = he[e];
            #pragma unroll
            for (int c = 0; c < 2; c++) {
                float4 w = sW2[k * 4 + half * 2 + c];
                o[c * 4 + 0] = fmaf(h, w.x, o[c * 4 + 0]);
                o[c * 4 + 1] = fmaf(h, w.y, o[c * 4 + 1]);
                o[c * 4 + 2] = fmaf(h, w.z, o[c * 4 + 2]);
                o[c * 4 + 3] = fmaf(h, w.w, o[c * 4 + 3]);
            }
        }
    }

    if (row0 + row < N) {
        float4* tr = reinterpret_cast<float4*>(g_t) +
                     (size_t)(row0 + row) * 4 + half * 2;
        tr[0] = make_float4(o[0], o[1], o[2], o[3]);
        tr[1] = make_float4(o[4], o[5], o[6], o[7]);
    }
}

// ---------------------------------------------------------------------------
// Layer-2 aggregation + bias + softmax, fused. 4 threads per node.
__global__ void __launch_bounds__(256) k_gather2_sm(const float* __restrict__ b2,
                                                    float* __restrict__ out,
                                                    int N) {
    int grp0 = blockIdx.x * 64 + (threadIdx.x >> 2);
    int q    = threadIdx.x & 3;
    int grp  = grp0 < N ? grp0 : N - 1;   // clamp so all lanes stay active for shfl
    bool valid = (grp0 < N);

    int degd = min(__ldg(&g_deg[grp]), CAP);
    const int* sl = g_slots + grp * CAP;
    const float4* t4 = reinterpret_cast<const float4*>(g_t);

    float4 acc = make_float4(0.f, 0.f, 0.f, 0.f);
    if (degd > 0) {
        int s = __ldg(sl);
        for (int j = 0; j < degd - 1; j++) {
            int snext = __ldg(sl + j + 1);
            float4 v = __ldg(t4 + (size_t)s * 4 + q);
            acc.x += v.x; acc.y += v.y; acc.z += v.z; acc.w += v.w;
            s = snext;
        }
        float4 v = __ldg(t4 + (size_t)s * 4 + q);
        acc.x += v.x; acc.y += v.y; acc.z += v.z; acc.w += v.w;
    }

    float4 bb = __ldg(reinterpret_cast<const float4*>(b2) + q);
    acc.x += bb.x; acc.y += bb.y; acc.z += bb.z; acc.w += bb.w;

    // softmax across the 16 logits held by 4 lanes
    float m = fmaxf(fmaxf(acc.x, acc.y), fmaxf(acc.z, acc.w));
    m = fmaxf(m, __shfl_xor_sync(0xffffffffu, m, 1, 4));
    m = fmaxf(m, __shfl_xor_sync(0xffffffffu, m, 2, 4));

    float4 ev;
    ev.x = __expf(acc.x - m); ev.y = __expf(acc.y - m);
    ev.z = __expf(acc.z - m); ev.w = __expf(acc.w - m);
    float sum = ev.x + ev.y + ev.z + ev.w;
    sum += __shfl_xor_sync(0xffffffffu, sum, 1, 4);
    sum += __shfl_xor_sync(0xffffffffu, sum, 2, 4);
    float inv = 1.f / sum;

    if (valid) {
        reinterpret_cast<float4*>(out)[(size_t)grp * 4 + q] =
            make_float4(ev.x * inv, ev.y * inv, ev.z * inv, ev.w * inv);
    }
}

// ---------------------------------------------------------------------------
extern "C" void kernel_launch(void* const* d_in, const int* in_sizes, int n_in,
                              void* d_out, int out_size) {
    const float* feat = (const float*)d_in[0];
    const float* W1   = (const float*)d_in[1];
    const float* b1   = (const float*)d_in[2];
    const float* W2   = (const float*)d_in[3];
    const float* b2   = (const float*)d_in[4];
    const int*   src  = (const int*)d_in[5];
    const int*   dst  = (const int*)d_in[6];

    int N = in_sizes[0] / 64;
    int E = in_sizes[5];

    k_zero_deg<<<(N + 255) / 256, 256>>>(N);
    k_bucket<<<(E + 255) / 256, 256>>>(src, dst, E);
    k_gather1<<<(N + 15) / 16, 256>>>(feat, N);
    k_mlp<<<(N + MLP_BR - 1) / MLP_BR, MLP_THR>>>(W1, b1, W2, N);
    k_gather2_sm<<<(N + 63) / 64, 256>>>(b2, (float*)d_out, N);
}

// round 11
// speedup vs baseline: 1.0623x; 1.0623x over previous
#include <cuda_runtime.h>

// GCN via bucket-then-gather (no float atomics):
//   1. k_zero_deg     : deg[] = 0
//   2. k_bucket       : per-dst buckets of src ids (int atomics for cursors)
//   3. k_gather1      : agg1[d] = sum_{e: dst=d} feat[src[e]]   (pure gather)
//   4. k_mlp          : t = relu(agg1@W1+b1) @ W2   (4-row tile + fma.f32x2)
//   5. k_gather2_sm   : out[d] = softmax(sum t[src] + b2)       (fused)

#define NMAX 100000
#define CAP  128   // max bucket size; dst-degree ~ Poisson(16), P(>=128) ~ 1e-70

__device__ int   g_deg  [NMAX];
__device__ int   g_slots[(size_t)NMAX * CAP];
__device__ __align__(16) float g_agg1[(size_t)NMAX * 64];
__device__ __align__(16) float g_t   [(size_t)NMAX * 16];

// ---- packed f32x2 helpers (sm_103a dual-FP32 path, PTX-only) ---------------
__device__ __forceinline__ unsigned long long pack2(float lo, float hi) {
    unsigned long long r;
    asm("mov.b64 %0, {%1, %2};" : "=l"(r) : "f"(lo), "f"(hi));
    return r;
}
__device__ __forceinline__ void unpack2(unsigned long long v, float& lo, float& hi) {
    asm("mov.b64 {%0, %1}, %2;" : "=f"(lo), "=f"(hi) : "l"(v));
}
__device__ __forceinline__ unsigned long long ffma2(unsigned long long a,
                                                    unsigned long long b,
                                                    unsigned long long c) {
    unsigned long long d;
    asm("fma.rn.f32x2 %0, %1, %2, %3;" : "=l"(d) : "l"(a), "l"(b), "l"(c));
    return d;
}

// ---------------------------------------------------------------------------
__global__ void k_zero_deg(int n) {
    int i = blockIdx.x * blockDim.x + threadIdx.x;
    if (i < n) g_deg[i] = 0;
}

// ---------------------------------------------------------------------------
__global__ void k_bucket(const int* __restrict__ src,
                         const int* __restrict__ dst, int E) {
    int e = blockIdx.x * blockDim.x + threadIdx.x;
    if (e >= E) return;
    int s = __ldg(src + e);
    int d = __ldg(dst + e);
    int pos = atomicAdd(&g_deg[d], 1);
    if (pos < CAP) g_slots[d * CAP + pos] = s;
}

// ---------------------------------------------------------------------------
// Layer-1 aggregation: 16 threads per node, one float4 column each.
__global__ void __launch_bounds__(256) k_gather1(const float* __restrict__ feat,
                                                 int N) {
    int grp  = blockIdx.x * 16 + (threadIdx.x >> 4);
    int q    = threadIdx.x & 15;
    if (grp >= N) return;

    int degd = min(__ldg(&g_deg[grp]), CAP);
    const int* sl = g_slots + grp * CAP;
    const float4* f4 = reinterpret_cast<const float4*>(feat);

    float4 acc = make_float4(0.f, 0.f, 0.f, 0.f);
    if (degd > 0) {
        int s = __ldg(sl);
        for (int j = 0; j < degd - 1; j++) {
            int snext = __ldg(sl + j + 1);          // prefetch next slot id
            float4 v = __ldg(f4 + (size_t)s * 16 + q);
            acc.x += v.x; acc.y += v.y; acc.z += v.z; acc.w += v.w;
            s = snext;
        }
        float4 v = __ldg(f4 + (size_t)s * 16 + q);
        acc.x += v.x; acc.y += v.y; acc.z += v.z; acc.w += v.w;
    }
    reinterpret_cast<float4*>(g_agg1)[(size_t)grp * 16 + q] = acc;
}

// ---------------------------------------------------------------------------
// MLP, v3: 128 threads / 128 rows per block. Thread (rg = tid>>2, q = tid&3)
// computes rows {rg, rg+32, rg+64, rg+96} x cols [q*16, q*16+16).
//   Per k-step: 4 weight LDS.128 (ulonglong2 -> f32x2 pairs, broadcast) +
//   1 x LDS.128 per 4 k per row; 32 FFMA2 (=64 FMA). LDS:FMA = 1:12.8
//   (was 1:3.9 -> smem-crossbar bound at 63.5us). FFMA2 halves issue slots.
// Row stride 32 keeps the 8 distinct x-addresses per warp conflict-free.
#define MLP_BR   128
#define MLP_THR  128
#define XSTR     17   // float4 row stride (68 floats)
#define MLP_SMEM ((MLP_BR * XSTR + 1024 + 256) * 16 + 256)

__global__ void __launch_bounds__(MLP_THR) k_mlp(const float* __restrict__ W1,
                                                 const float* __restrict__ b1,
                                                 const float* __restrict__ W2,
                                                 int N) {
    extern __shared__ float4 dsm[];
    float4* xs  = dsm;                       // MLP_BR * XSTR
    float4* sW1 = xs + MLP_BR * XSTR;        // 1024 float4 (64x64)
    float4* sW2 = sW1 + 1024;                // 256 float4  (64x16)
    float*  sb1 = reinterpret_cast<float*>(sW2 + 256);   // 64 floats

    int tid = threadIdx.x;
    for (int i = tid; i < 1024; i += MLP_THR)
        sW1[i] = __ldg(reinterpret_cast<const float4*>(W1) + i);
    for (int i = tid; i < 256; i += MLP_THR)
        sW2[i] = __ldg(reinterpret_cast<const float4*>(W2) + i);
    if (tid < 64) sb1[tid] = b1[tid];

    int row0 = blockIdx.x * MLP_BR;

    // Stage x tile (coalesced float4 reads).
    for (int i = tid; i < MLP_BR * 16; i += MLP_THR) {
        int r = i >> 4, c = i & 15;
        float4 v = make_float4(0.f, 0.f, 0.f, 0.f);
        if (row0 + r < N)
            v = __ldg(reinterpret_cast<const float4*>(g_agg1) +
                      (size_t)(row0 + r) * 16 + c);
        xs[r * XSTR + c] = v;
    }
    __syncthreads();

    int q  = tid & 3;    // col quarter: cols [q*16, q*16+16)
    int rg = tid >> 2;   // 0..31; rows rg + 32*r_i

    const ulonglong2* sW1p = reinterpret_cast<const ulonglong2*>(sW1);
    const ulonglong2* sW2p = reinterpret_cast<const ulonglong2*>(sW2);

    // ---- Layer 1: acc[r][pair] over 4 rows x 16 cols ----
    unsigned long long acc[4][8];
    #pragma unroll
    for (int j = 0; j < 8; j++) {
        unsigned long long bv = pack2(sb1[q * 16 + 2 * j], sb1[q * 16 + 2 * j + 1]);
        acc[0][j] = bv; acc[1][j] = bv; acc[2][j] = bv; acc[3][j] = bv;
    }

    #pragma unroll 1
    for (int k4 = 0; k4 < 16; k4++) {
        float4 xv0 = xs[(rg     ) * XSTR + k4];
        float4 xv1 = xs[(rg + 32) * XSTR + k4];
        float4 xv2 = xs[(rg + 64) * XSTR + k4];
        float4 xv3 = xs[(rg + 96) * XSTR + k4];
        float x0e[4] = {xv0.x, xv0.y, xv0.z, xv0.w};
        float x1e[4] = {xv1.x, xv1.y, xv1.z, xv1.w};
        float x2e[4] = {xv2.x, xv2.y, xv2.z, xv2.w};
        float x3e[4] = {xv3.x, xv3.y, xv3.z, xv3.w};
        #pragma unroll
        for (int e = 0; e < 4; e++) {
            int k = k4 * 4 + e;
            unsigned long long x0 = pack2(x0e[e], x0e[e]);
            unsigned long long x1 = pack2(x1e[e], x1e[e]);
            unsigned long long x2 = pack2(x2e[e], x2e[e]);
            unsigned long long x3 = pack2(x3e[e], x3e[e]);
            #pragma unroll
            for (int j4 = 0; j4 < 4; j4++) {
                ulonglong2 w = sW1p[k * 16 + q * 4 + j4];
                acc[0][2*j4  ] = ffma2(x0, w.x, acc[0][2*j4  ]);
                acc[0][2*j4+1] = ffma2(x0, w.y, acc[0][2*j4+1]);
                acc[1][2*j4  ] = ffma2(x1, w.x, acc[1][2*j4  ]);
                acc[1][2*j4+1] = ffma2(x1, w.y, acc[1][2*j4+1]);
                acc[2][2*j4  ] = ffma2(x2, w.x, acc[2][2*j4  ]);
                acc[2][2*j4+1] = ffma2(x2, w.y, acc[2][2*j4+1]);
                acc[3][2*j4  ] = ffma2(x3, w.x, acc[3][2*j4  ]);
                acc[3][2*j4+1] = ffma2(x3, w.y, acc[3][2*j4+1]);
            }
        }
    }

    // ---- ReLU + write h back into x tile ----
    __syncthreads();
    #pragma unroll
    for (int r = 0; r < 4; r++) {
        int row = rg + 32 * r;
        #pragma unroll
        for (int j4 = 0; j4 < 4; j4++) {
            float a, b, c, d;
            unpack2(acc[r][2*j4  ], a, b);
            unpack2(acc[r][2*j4+1], c, d);
            xs[row * XSTR + q * 4 + j4] =
                make_float4(fmaxf(a, 0.f), fmaxf(b, 0.f),
                            fmaxf(c, 0.f), fmaxf(d, 0.f));
        }
    }
    __syncthreads();

    // ---- Layer 2: 4 rows x cols [q*4, q*4+4) ----
    unsigned long long o[4][2];
    #pragma unroll
    for (int r = 0; r < 4; r++) { o[r][0] = 0ULL; o[r][1] = 0ULL; }

    #pragma unroll 1
    for (int k4 = 0; k4 < 16; k4++) {
        float4 hv0 = xs[(rg     ) * XSTR + k4];
        float4 hv1 = xs[(rg + 32) * XSTR + k4];
        float4 hv2 = xs[(rg + 64) * XSTR + k4];
        float4 hv3 = xs[(rg + 96) * XSTR + k4];
        float h0e[4] = {hv0.x, hv0.y, hv0.z, hv0.w};
        float h1e[4] = {hv1.x, hv1.y, hv1.z, hv1.w};
        float h2e[4] = {hv2.x, hv2.y, hv2.z, hv2.w};
        float h3e[4] = {hv3.x, hv3.y, hv3.z, hv3.w};
        #pragma unroll
        for (int e = 0; e < 4; e++) {
            int k = k4 * 4 + e;
            ulonglong2 w = sW2p[k * 4 + q];
            unsigned long long x0 = pack2(h0e[e], h0e[e]);
            unsigned long long x1 = pack2(h1e[e], h1e[e]);
            unsigned long long x2 = pack2(h2e[e], h2e[e]);
            unsigned long long x3 = pack2(h3e[e], h3e[e]);
            o[0][0] = ffma2(x0, w.x, o[0][0]);  o[0][1] = ffma2(x0, w.y, o[0][1]);
            o[1][0] = ffma2(x1, w.x, o[1][0]);  o[1][1] = ffma2(x1, w.y, o[1][1]);
            o[2][0] = ffma2(x2, w.x, o[2][0]);  o[2][1] = ffma2(x2, w.y, o[2][1]);
            o[3][0] = ffma2(x3, w.x, o[3][0]);  o[3][1] = ffma2(x3, w.y, o[3][1]);
        }
    }

    #pragma unroll
    for (int r = 0; r < 4; r++) {
        int row = row0 + rg + 32 * r;
        if (row < N) {
            float a, b, c, d;
            unpack2(o[r][0], a, b);
            unpack2(o[r][1], c, d);
            reinterpret_cast<float4*>(g_t)[(size_t)row * 4 + q] =
                make_float4(a, b, c, d);
        }
    }
}

// ---------------------------------------------------------------------------
// Layer-2 aggregation + bias + softmax, fused. 4 threads per node.
__global__ void __launch_bounds__(256) k_gather2_sm(const float* __restrict__ b2,
                                                    float* __restrict__ out,
                                                    int N) {
    int grp0 = blockIdx.x * 64 + (threadIdx.x >> 2);
    int q    = threadIdx.x & 3;
    int grp  = grp0 < N ? grp0 : N - 1;   // clamp so all lanes stay active for shfl
    bool valid = (grp0 < N);

    int degd = min(__ldg(&g_deg[grp]), CAP);
    const int* sl = g_slots + grp * CAP;
    const float4* t4 = reinterpret_cast<const float4*>(g_t);

    float4 acc = make_float4(0.f, 0.f, 0.f, 0.f);
    if (degd > 0) {
        int s = __ldg(sl);
        for (int j = 0; j < degd - 1; j++) {
            int snext = __ldg(sl + j + 1);
            float4 v = __ldg(t4 + (size_t)s * 4 + q);
            acc.x += v.x; acc.y += v.y; acc.z += v.z; acc.w += v.w;
            s = snext;
        }
        float4 v = __ldg(t4 + (size_t)s * 4 + q);
        acc.x += v.x; acc.y += v.y; acc.z += v.z; acc.w += v.w;
    }

    float4 bb = __ldg(reinterpret_cast<const float4*>(b2) + q);
    acc.x += bb.x; acc.y += bb.y; acc.z += bb.z; acc.w += bb.w;

    // softmax across the 16 logits held by 4 lanes
    float m = fmaxf(fmaxf(acc.x, acc.y), fmaxf(acc.z, acc.w));
    m = fmaxf(m, __shfl_xor_sync(0xffffffffu, m, 1, 4));
    m = fmaxf(m, __shfl_xor_sync(0xffffffffu, m, 2, 4));

    float4 ev;
    ev.x = __expf(acc.x - m); ev.y = __expf(acc.y - m);
    ev.z = __expf(acc.z - m); ev.w = __expf(acc.w - m);
    float sum = ev.x + ev.y + ev.z + ev.w;
    sum += __shfl_xor_sync(0xffffffffu, sum, 1, 4);
    sum += __shfl_xor_sync(0xffffffffu, sum, 2, 4);
    float inv = 1.f / sum;

    if (valid) {
        reinterpret_cast<float4*>(out)[(size_t)grp * 4 + q] =
            make_float4(ev.x * inv, ev.y * inv, ev.z * inv, ev.w * inv);
    }
}

// ---------------------------------------------------------------------------
extern "C" void kernel_launch(void* const* d_in, const int* in_sizes, int n_in,
                              void* d_out, int out_size) {
    const float* feat = (const float*)d_in[0];
    const float* W1   = (const float*)d_in[1];
    const float* b1   = (const float*)d_in[2];
    const float* W2   = (const float*)d_in[3];
    const float* b2   = (const float*)d_in[4];
    const int*   src  = (const int*)d_in[5];
    const int*   dst  = (const int*)d_in[6];

    int N = in_sizes[0] / 64;
    int E = in_sizes[5];

    // >48KB dynamic smem needs an opt-in (attribute set, not an allocation;
    // idempotent, capture-legal).
    cudaFuncSetAttribute(k_mlp, cudaFuncAttributeMaxDynamicSharedMemorySize,
                         MLP_SMEM);

    k_zero_deg<<<(N + 255) / 256, 256>>>(N);
    k_bucket<<<(E + 255) / 256, 256>>>(src, dst, E);
    k_gather1<<<(N + 15) / 16, 256>>>(feat, N);
    k_mlp<<<(N + MLP_BR - 1) / MLP_BR, MLP_THR, MLP_SMEM>>>(W1, b1, W2, N);
    k_gather2_sm<<<(N + 63) / 64, 256>>>(b2, (float*)d_out, N);
}